// round 15
// baseline (speedup 1.0000x reference)
#include <cuda_runtime.h>
#include <math.h>

// ---------------------------------------------------------------------------
// Mie scattering, table-based v9:
//   1) reduce:      pure sum of d; 1152 blocks x 256 thr x 4 float4/thread
//   2) coeff+table: 9 blocks; mean -> double Mie coefficients -> fp32 p,q ->
//                   per-interval CUBIC POLYNOMIAL COEFFICIENTS (c0..c3) for
//                   s in [-0.5, 0.5]  (from 4 fp32-recurrence taps, in smem)
//   3) main:        grid-stride float4; per element: magic-number index +
//                   one LDS.128 + 3 FMA Horner
// ---------------------------------------------------------------------------

#define N_TERMS    50
#define RED_BLOCKS 1152
#define RED_THREADS 256
#define TABLE_N    2048                 // intervals over [0, pi]
#define TABLE_PTS  (TABLE_N + 4)        // scalar points 0..2051
#define TABLE_ENTRIES (TABLE_N + 1)     // coeff entries 0..2048
#define CT_BLOCKS  9                    // coeff+table blocks (256 entries each)
#define MAIN_BLOCKS 888                 // 6 resident blocks x 148 SMs

static __device__ double g_partials[RED_BLOCKS];
static __device__ float4 g_coef[TABLE_ENTRIES];   // (c0, c1, c2, c3)

// ---------------- Stage 1: partial sums of d (pure stream) ------------------
__global__ void mie_reduce_kernel(const float* __restrict__ d, int n) {
    __shared__ double sh[RED_THREADS];
    float a0 = 0.f, a1 = 0.f, a2 = 0.f, a3 = 0.f;
    int n4 = n >> 2;
    const float4* __restrict__ d4 = (const float4*)d;
    int T   = gridDim.x * blockDim.x;
    int gid = blockIdx.x * blockDim.x + threadIdx.x;

    if (n4 == T * 4) {                 // benchmark shape: exactly 4 float4/thread
        float4 v0 = d4[gid];
        float4 v1 = d4[gid + T];
        float4 v2 = d4[gid + 2 * T];
        float4 v3 = d4[gid + 3 * T];
        a0 = (v0.x + v1.x) + (v2.x + v3.x);
        a1 = (v0.y + v1.y) + (v2.y + v3.y);
        a2 = (v0.z + v1.z) + (v2.z + v3.z);
        a3 = (v0.w + v1.w) + (v2.w + v3.w);
    } else {
        for (int i = gid; i < n4; i += T) {
            float4 v = d4[i];
            a0 += v.x; a1 += v.y; a2 += v.z; a3 += v.w;
        }
        for (int i = (n4 << 2) + gid; i < n; i += T)
            a0 += d[i];
    }

    sh[threadIdx.x] = ((double)a0 + (double)a1) + ((double)a2 + (double)a3);
    __syncthreads();
    for (int s = RED_THREADS / 2; s > 0; s >>= 1) {
        if (threadIdx.x < s) sh[threadIdx.x] += sh[threadIdx.x + s];
        __syncthreads();
    }
    if (threadIdx.x == 0) g_partials[blockIdx.x] = sh[0];
}

// ------- Stage 2: mean + coefficients (redundant per block) + poly table ----
__global__ void mie_coeff_table_kernel(int n_total) {
    __shared__ double sh[256];
    __shared__ double jx[N_TERMS + 1], yx[N_TERMS + 1], jmx[N_TERMS + 1];
    __shared__ double shx, shmx, sinvx, sinvmx;
    __shared__ float4 spq[N_TERMS];     // fp32 (p.re, p.im, q.re, q.im)
    __shared__ float  spt[260];         // point values: chunk entries + halo
    int t = threadIdx.x;

    // ---- deterministic mean (every block computes the same value) ----
    double s = 0.0;
    for (int i = t; i < RED_BLOCKS; i += 256) s += g_partials[i];
    sh[t] = s;
    __syncthreads();
    for (int w = 128; w > 0; w >>= 1) {
        if (t < w) sh[t] += sh[t + w];
        __syncthreads();
    }

    if (t == 0) {
        // x_mean = mean(d) * pi_f / lambda_f in double, rounded to fp32
        double dmean = sh[0] / (double)n_total;
        float xmf = (float)(dmean * (double)3.14159274101257324f /
                            (double)5.5e-7f);
        float mxf = __fmul_rn(1.31f, xmf);              // fp32 m*x
        double x  = (double)xmf;
        double mx = (double)mxf;
        double invx  = 1.0 / x;          // only 2 serial fp64 divides
        double invmx = 1.0 / mx;
        shx = x; shmx = mx; sinvx = invx; sinvmx = invmx;

        double sx = sin(x),  cx = cos(x);
        double smx = sin(mx), cmx = cos(mx);
        jx[0]  = sx * invx;
        jx[1]  = sx * invx * invx - cx * invx;
        yx[0]  = -cx * invx;
        yx[1]  = -cx * invx * invx - sx * invx;
        jmx[0] = smx * invmx;
        jmx[1] = smx * invmx * invmx - cmx * invmx;
        for (int k = 1; k < N_TERMS; k++) {
            double c  = (2.0 * k + 1.0) * invx;
            double cm = (2.0 * k + 1.0) * invmx;
            jx[k + 1]  = c  * jx[k]  - jx[k - 1];
            yx[k + 1]  = c  * yx[k]  - yx[k - 1];
            jmx[k + 1] = cm * jmx[k] - jmx[k - 1];
        }
    }
    __syncthreads();

    if (t < N_TERMS) {
        int n = t + 1;
        double dn = (double)n;
        double x = shx, invx = sinvx, invmx = sinvmx;
        double m = (double)1.31f;

        double jn  = jx[n],  jn1 = jx[n - 1];
        double yn  = yx[n],  yn1 = yx[n - 1];
        double jm  = jmx[n], jm1 = jmx[n - 1];

        double dj = jm1 - (dn + 1.0) * invmx * jm;
        double D  = dj / (jm + 1e-10);

        double psi  = x * jn,  psi1 = x * jn1;
        double chi  = x * yn,  chi1 = x * yn1;   // xi = psi + i*chi

        double nx = dn * invx;
        double fa = D / m + nx;
        double fb = m * D + nx;

        double numa = fa * psi - psi1;
        double dar  = numa + 1e-10;
        double dai  = fa * chi - chi1;
        double ia   = 1.0 / (dar * dar + dai * dai);
        double ar   = numa * dar * ia;
        double ai   = -numa * dai * ia;

        double numb = fb * psi - psi1;
        double dbr  = numb + 1e-10;
        double dbi  = fb * chi - chi1;
        double ib   = 1.0 / (dbr * dbr + dbi * dbi);
        double br   = numb * dbr * ib;
        double bi   = -numb * dbi * ib;

        double cc = 0.5 * (2.0 * dn + 1.0) / (dn * (dn + 1.0));
        spq[t] = make_float4((float)(cc * (ar + br)), (float)(cc * (ai + bi)),
                             (float)(cc * (ar - br)), (float)(cc * (ai - bi)));
    }
    __syncthreads();

    // ---- this block's chunk: point values (with halo) then coefficients ----
    int base = blockIdx.x * 256;                       // first entry of chunk
    int n_entries = min(256, TABLE_ENTRIES - base);
    if (n_entries <= 0) return;
    int n_pts = n_entries + 3;                         // points base-1 .. base+n_entries+1

    const double H = 3.14159265358979323846 / (double)TABLE_N;
    const float SCALE = (float)(5.5e-7 * 5.5e-7 /
        (4.0 * 3.14159265358979323846 * 3.14159265358979323846));

    for (int k = t; k < n_pts; k += 256) {
        int gi = base - 1 + k;
        if (gi < 0) gi = 0;                            // entry 0 never accessed
        double thd = (double)gi * H;
        float c  = (float)cos(thd);
        float st = (float)sin(thd) + 1e-10f;
        float inv_s = 1.0f / st;
        float pi1 = -sqrtf(fmaxf(1.0f - c * c, 0.0f)) * inv_s;

        // n = 1: tau_1 = c (reference's where-branch)
        float4 w = spq[0];
        float u = pi1 + c, v = pi1 - c;
        float Ar = w.x * u, Ai = w.y * u;
        float Br = w.z * v, Bi = w.w * v;

        float qp = pi1;               // pi_{n-1}
        float qc = 3.0f * c * pi1;    // pi_2  (pi_0 = 0)

#pragma unroll
        for (int nn = 2; nn <= N_TERMS; nn++) {
            const float nf   = (float)nn;
            const float np1  = (float)(nn + 1);
            const float invn = 1.0f / (float)nn;   // compile-time constant

            float t1 = c * qc;
            float ta = fmaf(nf, t1, -np1 * qp);    // tau_n
            float uu = qc + ta;
            float vv = qc - ta;

            w = spq[nn - 1];
            Ar = fmaf(w.x, uu, Ar);
            Ai = fmaf(w.y, uu, Ai);
            Br = fmaf(w.z, vv, Br);
            Bi = fmaf(w.w, vv, Bi);

            float qn = fmaf(np1, t1, ta) * invn;   // pi_{n+1}
            qp = qc; qc = qn;
        }
        spt[k] = (Ar * Ar + Ai * Ai + Br * Br + Bi * Bi) * SCALE;
    }
    __syncthreads();

    // coefficients for entry j = base + t from points {j-1, j, j+1, j+2}
    if (t < n_entries) {
        float fm1 = spt[t];
        float f0  = spt[t + 1];
        float f1  = spt[t + 2];
        float f2  = spt[t + 3];
        float c0 = f0;
        float c2 = 0.5f * ((f1 + fm1) - 2.0f * f0);
        float c3 = (f2 - 3.0f * f1 + 3.0f * f0 - fm1) * 0.16666667f;
        float c1 = 0.5f * (f1 - fm1) - c3;
        g_coef[base + t] = make_float4(c0, c1, c2, c3);
    }
}

// ---------------- Stage 3: 3-FMA Horner from coefficient table --------------
// MAGIC = 2^23 + 2^22: for 0 <= t < 2^22, (t + MAGIC) has fixed exponent and
// its low mantissa bits equal round-to-nearest(t).
#define MAGIC_F 12582912.0f

__device__ __forceinline__ float interp4(const float4* __restrict__ T,
                                         float th, float inv_h) {
    float ft = fmaf(th, inv_h, MAGIC_F);         // index in low mantissa bits
    float jf = ft - MAGIC_F;                     // (float)round(t)
    float s  = fmaf(th, inv_h, -jf);             // s in [-0.5, 0.5]
    int   j  = (int)(__float_as_uint(ft) & 0x3FFFFFu);
    // theta in [0.01, pi-0.01]  =>  j in [6, 2042]: entries in range

    float4 c = T[j];                             // one LDS.128: c0..c3
    return fmaf(fmaf(fmaf(c.w, s, c.z), s, c.y), s, c.x);
}

__global__ void __launch_bounds__(256) mie_main_kernel(
    const float* __restrict__ theta, float* __restrict__ out, int n)
{
    __shared__ float4 Ts4[TABLE_ENTRIES];   // 32.8 KB
    for (int i = threadIdx.x; i < TABLE_ENTRIES; i += 256)
        Ts4[i] = g_coef[i];                 // coalesced LDG.128
    __syncthreads();

    const float INV_H = (float)TABLE_N / 3.14159265358979323846f;
    int n4 = n >> 2;
    const float4* __restrict__ th4 = (const float4*)theta;
    float4* __restrict__ out4 = (float4*)out;
    int stride = gridDim.x * blockDim.x;

    for (int i4 = blockIdx.x * blockDim.x + threadIdx.x; i4 < n4; i4 += stride) {
        float4 v = th4[i4];
        float4 r;
        r.x = interp4(Ts4, v.x, INV_H);
        r.y = interp4(Ts4, v.y, INV_H);
        r.z = interp4(Ts4, v.z, INV_H);
        r.w = interp4(Ts4, v.w, INV_H);
        out4[i4] = r;
    }

    // scalar remainder (n % 4), block 0 only
    if (blockIdx.x == 0 && threadIdx.x == 0) {
        for (int e = n4 << 2; e < n; e++)
            out[e] = interp4(Ts4, theta[e], INV_H);
    }
}

// ---------------------------------------------------------------------------
extern "C" void kernel_launch(void* const* d_in, const int* in_sizes, int n_in,
                              void* d_out, int out_size) {
    const float* d     = (const float*)d_in[0];
    const float* theta = (const float*)d_in[1];
    float* out = (float*)d_out;
    int n = in_sizes[0];

    mie_reduce_kernel<<<RED_BLOCKS, RED_THREADS>>>(d, n);
    mie_coeff_table_kernel<<<CT_BLOCKS, 256>>>(n);
    mie_main_kernel<<<MAIN_BLOCKS, 256>>>(theta, out, n);
}